// round 9
// baseline (speedup 1.0000x reference)
#include <cuda_runtime.h>

typedef unsigned long long u64;

#define TT 512          // sequence length
#define HH 8            // hidden size

// ---- packed f32x2 helpers ----
static __device__ __forceinline__ u64 pk2(float lo, float hi) {
    u64 r; asm("mov.b64 %0, {%1,%2};" : "=l"(r) : "f"(lo), "f"(hi)); return r;
}
static __device__ __forceinline__ void upk2(u64 v, float& lo, float& hi) {
    asm("mov.b64 {%0,%1}, %2;" : "=f"(lo), "=f"(hi) : "l"(v));
}
static __device__ __forceinline__ u64 ffma2(u64 a, u64 b, u64 c) {
    u64 d; asm("fma.rn.f32x2 %0,%1,%2,%3;" : "=l"(d) : "l"(a), "l"(b), "l"(c)); return d;
}
static __device__ __forceinline__ u64 fmul2(u64 a, u64 b) {
    u64 d; asm("mul.rn.f32x2 %0,%1,%2;" : "=l"(d) : "l"(a), "l"(b)); return d;
}
static __device__ __forceinline__ u64 fadd2(u64 a, u64 b) {
    u64 d; asm("add.rn.f32x2 %0,%1,%2;" : "=l"(d) : "l"(a), "l"(b)); return d;
}
static __device__ __forceinline__ float tanhap(float x) {
    float y; asm("tanh.approx.f32 %0,%1;" : "=f"(y) : "f"(x)); return y;
}
static __device__ __forceinline__ u64 bfly64(u64 v, int m) {
    return __shfl_xor_sync(0xffffffffu, v, m);
}
// activation: sigmoid rows pre-scaled 0.5 -> 0.5*tanh+0.5 ; tanh rows -> tanh
static __device__ __forceinline__ u64 act2(u64 g, float kA, float kB) {
    float a, b; upk2(g, a, b);
    return pk2(fmaf(kA, tanhap(a), kB), fmaf(kA, tanhap(b), kB));
}
static __device__ __forceinline__ u64 tanh2(u64 c) {
    float a, b; upk2(c, a, b);
    return pk2(tanhap(a), tanhap(b));
}

// Layout: 1 warp/block = 2 groups of 16 lanes; each group = 2 batches packed
// in f32x2 halves. Within a group, lane s: k = s&7.
//   s<8  (lo): owns rows {k (i), 16+k (g)}  -> computes i*g locally
//   s>=8 (hi): owns rows {8+k (f), 24+k (o)} -> computes f*c locally, owns c,h
// One bfly(8) exchanges ig<->fc; c = ig + fc on both lanes.
// h published via smem (predicated STS.64 by hi lanes), double-buffered by
// step parity, ONE __syncwarp per step, read back as broadcast LDS.128.
// Pipeline is SKEWED: body(t) computes L1(t) and L2(t-1) — independent chains.
__global__ void __launch_bounds__(32)
lstm2_kernel(const float* __restrict__ x,
             const float* __restrict__ W_ih1, const float* __restrict__ W_hh1,
             const float* __restrict__ b_ih1, const float* __restrict__ b_hh1,
             const float* __restrict__ W_ih2, const float* __restrict__ W_hh2,
             const float* __restrict__ b_ih2, const float* __restrict__ b_hh2,
             const float* __restrict__ W_fc,  const float* __restrict__ b_fc,
             float* __restrict__ out, int B)
{
    // [layer][parity][group][k] — 512 B
    __shared__ __align__(16) u64 sh[2][2][2][HH];

    const int L   = threadIdx.x;
    const int grp = L >> 4;
    const int s   = L & 15;
    const int k   = s & 7;
    const bool hi = (s >= 8);

    if (blockIdx.x * 4 + 3 >= B) return;   // warp-uniform guard (B%4==0 here)

    const int b0 = blockIdx.x * 4 + grp * 2;
    const int b1 = b0 + 1;

    const int r0 = hi ? (8 + k)  : k;         // f : i   (both sigmoid)
    const int r1 = hi ? (24 + k) : (16 + k);  // o : g
    const float pre1 = hi ? 0.5f : 1.0f;      // sigmoid half-angle vs tanh
    const float kA1  = pre1;
    const float kB1  = hi ? 0.5f : 0.0f;

    // ---- dup-packed, pre-scaled weights (registers) ----
    u64 wx0, wx1, bb0, bb1, cb0, cb1;
    {
        float a = W_ih1[r0] * 0.5f;  wx0 = pk2(a, a);
        float b = W_ih1[r1] * pre1;  wx1 = pk2(b, b);
        float c = (b_ih1[r0] + b_hh1[r0]) * 0.5f;  bb0 = pk2(c, c);
        float d = (b_ih1[r1] + b_hh1[r1]) * pre1;  bb1 = pk2(d, d);
        float e = (b_ih2[r0] + b_hh2[r0]) * 0.5f;  cb0 = pk2(e, e);
        float f = (b_ih2[r1] + b_hh2[r1]) * pre1;  cb1 = pk2(f, f);
    }
    u64 wh1a[HH], wh1b[HH], wi2a[HH], wi2b[HH], wh2a[HH], wh2b[HH];
#pragma unroll
    for (int j = 0; j < HH; j++) {
        float a = W_hh1[r0 * HH + j] * 0.5f;  wh1a[j] = pk2(a, a);
        float b = W_hh1[r1 * HH + j] * pre1;  wh1b[j] = pk2(b, b);
        float c = W_ih2[r0 * HH + j] * 0.5f;  wi2a[j] = pk2(c, c);
        float d = W_ih2[r1 * HH + j] * pre1;  wi2b[j] = pk2(d, d);
        float e = W_hh2[r0 * HH + j] * 0.5f;  wh2a[j] = pk2(e, e);
        float f = W_hh2[r1 * HH + j] * pre1;  wh2b[j] = pk2(f, f);
    }

    // ---- state ----
    u64 h1v[HH], h2v[HH];
#pragma unroll
    for (int j = 0; j < HH; j++) { h1v[j] = 0ull; h2v[j] = 0ull; }
    u64 c1 = 0ull, c2 = 0ull;

    const float* xr0 = x + (size_t)b0 * TT;
    const float* xr1 = x + (size_t)b1 * TT;

    // Layer-1 gate step: consumes xp + h1v, updates c1, returns h1 (valid on hi)
    auto l1 = [&](u64 xp) -> u64 {
        u64 e0 = ffma2(wx0, xp, bb0);
        u64 o0 = fmul2(wh1a[1], h1v[1]);
        u64 e1 = ffma2(wx1, xp, bb1);
        u64 o1 = fmul2(wh1b[1], h1v[1]);
        e0 = ffma2(wh1a[0], h1v[0], e0);  o0 = ffma2(wh1a[3], h1v[3], o0);
        e1 = ffma2(wh1b[0], h1v[0], e1);  o1 = ffma2(wh1b[3], h1v[3], o1);
        e0 = ffma2(wh1a[2], h1v[2], e0);  o0 = ffma2(wh1a[5], h1v[5], o0);
        e1 = ffma2(wh1b[2], h1v[2], e1);  o1 = ffma2(wh1b[5], h1v[5], o1);
        e0 = ffma2(wh1a[4], h1v[4], e0);  o0 = ffma2(wh1a[7], h1v[7], o0);
        e1 = ffma2(wh1b[4], h1v[4], e1);  o1 = ffma2(wh1b[7], h1v[7], o1);
        e0 = ffma2(wh1a[6], h1v[6], e0);
        e1 = ffma2(wh1b[6], h1v[6], e1);
        u64 a0 = act2(fadd2(e0, o0), 0.5f, 0.5f);  // i (lo) or f (hi)
        u64 a1 = act2(fadd2(e1, o1), kA1, kB1);    // g (lo) or o (hi)
        u64 op   = hi ? c1 : a1;                   // f*c (hi) or i*g (lo)
        u64 prod = fmul2(a0, op);
        u64 yy   = bfly64(prod, 8);                // ig <-> fc
        c1 = fadd2(prod, yy);
        return fmul2(a1, tanh2(c1));               // o*tanh(c) valid on hi
    };

    // Layer-2 gate step: consumes h1v + h2v, updates c2, returns h2 (valid on hi)
    auto l2 = [&]() -> u64 {
        u64 e0 = ffma2(wi2a[0], h1v[0], cb0);
        u64 o0 = fmul2(wi2a[1], h1v[1]);
        u64 e1 = ffma2(wi2b[0], h1v[0], cb1);
        u64 o1 = fmul2(wi2b[1], h1v[1]);
        e0 = ffma2(wi2a[2], h1v[2], e0);  o0 = ffma2(wi2a[3], h1v[3], o0);
        e1 = ffma2(wi2b[2], h1v[2], e1);  o1 = ffma2(wi2b[3], h1v[3], o1);
        e0 = ffma2(wi2a[4], h1v[4], e0);  o0 = ffma2(wi2a[5], h1v[5], o0);
        e1 = ffma2(wi2b[4], h1v[4], e1);  o1 = ffma2(wi2b[5], h1v[5], o1);
        e0 = ffma2(wi2a[6], h1v[6], e0);  o0 = ffma2(wi2a[7], h1v[7], o0);
        e1 = ffma2(wi2b[6], h1v[6], e1);  o1 = ffma2(wi2b[7], h1v[7], o1);
        e0 = ffma2(wh2a[0], h2v[0], e0);  o0 = ffma2(wh2a[1], h2v[1], o0);
        e1 = ffma2(wh2b[0], h2v[0], e1);  o1 = ffma2(wh2b[1], h2v[1], o1);
        e0 = ffma2(wh2a[2], h2v[2], e0);  o0 = ffma2(wh2a[3], h2v[3], o0);
        e1 = ffma2(wh2b[2], h2v[2], e1);  o1 = ffma2(wh2b[3], h2v[3], o1);
        e0 = ffma2(wh2a[4], h2v[4], e0);  o0 = ffma2(wh2a[5], h2v[5], o0);
        e1 = ffma2(wh2b[4], h2v[4], e1);  o1 = ffma2(wh2b[5], h2v[5], o1);
        e0 = ffma2(wh2a[6], h2v[6], e0);  o0 = ffma2(wh2a[7], h2v[7], o0);
        e1 = ffma2(wh2b[6], h2v[6], e1);  o1 = ffma2(wh2b[7], h2v[7], o1);
        u64 a0 = act2(fadd2(e0, o0), 0.5f, 0.5f);
        u64 a1 = act2(fadd2(e1, o1), kA1, kB1);
        u64 op   = hi ? c2 : a1;
        u64 prod = fmul2(a0, op);
        u64 yy   = bfly64(prod, 8);
        c2 = fadd2(prod, yy);
        return fmul2(a1, tanh2(c2));
    };

    // x double-buffer
    float xa = xr0[0], xb = xr1[0];

    // ---- prologue: L1(0) only ----
    {
        float xan = xr0[1], xbn = xr1[1];
        u64 hp1 = l1(pk2(xa, xb));
        if (hi) sh[0][0][grp][k] = hp1;
        __syncwarp();
        const ulonglong2* q = (const ulonglong2*)&sh[0][0][grp][0];
        ulonglong2 v0 = q[0], v1 = q[1], v2 = q[2], v3 = q[3];
        h1v[0] = v0.x; h1v[1] = v0.y; h1v[2] = v1.x; h1v[3] = v1.y;
        h1v[4] = v2.x; h1v[5] = v2.y; h1v[6] = v3.x; h1v[7] = v3.y;
        xa = xan; xb = xbn;
    }

    // ---- main loop: body(t) = L1(t) + L2(t-1), t = 1..TT-1 ----
#pragma unroll 8
    for (int t = 1; t < TT; ++t) {
        int tn = (t + 1 < TT) ? (t + 1) : 0;      // prefetch index (dummy ok)
        float xan = xr0[tn], xbn = xr1[tn];
        const int p = t & 1;

        u64 hp1 = l1(pk2(xa, xb));                // L1(t): uses h1v = h1(t-1)
        u64 hp2 = l2();                           // L2(t-1): h1(t-1), h2(t-2)

        if (hi) { sh[0][p][grp][k] = hp1; sh[1][p ^ 1][grp][k] = hp2; }
        __syncwarp();
        {
            const ulonglong2* q = (const ulonglong2*)&sh[0][p][grp][0];
            ulonglong2 v0 = q[0], v1 = q[1], v2 = q[2], v3 = q[3];
            h1v[0] = v0.x; h1v[1] = v0.y; h1v[2] = v1.x; h1v[3] = v1.y;
            h1v[4] = v2.x; h1v[5] = v2.y; h1v[6] = v3.x; h1v[7] = v3.y;
        }
        {
            const ulonglong2* q = (const ulonglong2*)&sh[1][p ^ 1][grp][0];
            ulonglong2 v0 = q[0], v1 = q[1], v2 = q[2], v3 = q[3];
            h2v[0] = v0.x; h2v[1] = v0.y; h2v[2] = v1.x; h2v[3] = v1.y;
            h2v[4] = v2.x; h2v[5] = v2.y; h2v[6] = v3.x; h2v[7] = v3.y;
        }
        xa = xan; xb = xbn;
    }

    // ---- epilogue: L2(TT-1) ----
    {
        u64 hp2 = l2();                            // uses h1(511), h2(510)
        if (hi) sh[1][1][grp][k] = hp2;
        __syncwarp();
        const ulonglong2* q = (const ulonglong2*)&sh[1][1][grp][0];
        ulonglong2 v0 = q[0], v1 = q[1], v2 = q[2], v3 = q[3];
        h2v[0] = v0.x; h2v[1] = v0.y; h2v[2] = v1.x; h2v[3] = v1.y;
        h2v[4] = v2.x; h2v[5] = v2.y; h2v[6] = v3.x; h2v[7] = v3.y;
    }

    // ======== FC: out[b, m] = sum_j W_fc[m,j] * h2[j] + b_fc[m] ========
    if (s < 4) {
        float bf = b_fc[s];
        u64 acc = pk2(bf, bf);
#pragma unroll
        for (int j = 0; j < HH; j++) {
            float w = W_fc[s * HH + j];
            acc = ffma2(pk2(w, w), h2v[j], acc);
        }
        float q0, q1; upk2(acc, q0, q1);
        out[b0 * 4 + s] = q0;
        out[b1 * 4 + s] = q1;
    }
}

extern "C" void kernel_launch(void* const* d_in, const int* in_sizes, int n_in,
                              void* d_out, int out_size)
{
    const float* x     = (const float*)d_in[0];
    const float* W_ih1 = (const float*)d_in[1];
    const float* W_hh1 = (const float*)d_in[2];
    const float* b_ih1 = (const float*)d_in[3];
    const float* b_hh1 = (const float*)d_in[4];
    const float* W_ih2 = (const float*)d_in[5];
    const float* W_hh2 = (const float*)d_in[6];
    const float* b_ih2 = (const float*)d_in[7];
    const float* b_hh2 = (const float*)d_in[8];
    const float* W_fc  = (const float*)d_in[9];
    const float* b_fc  = (const float*)d_in[10];
    float* out = (float*)d_out;

    int B = in_sizes[0] / TT;              // 4096
    int blocks = (B + 3) / 4;              // 4 batch elements per 1-warp block

    lstm2_kernel<<<blocks, 32>>>(x, W_ih1, W_hh1, b_ih1, b_hh1,
                                 W_ih2, W_hh2, b_ih2, b_hh2,
                                 W_fc, b_fc, out, B);
}